// round 6
// baseline (speedup 1.0000x reference)
#include <cuda_runtime.h>
#include <cstdint>
#include <mma.h>

using namespace nvcuda;

#define SEQ   2048
#define DIMSZ 4096
#define NHEAD 32
#define HDIM  128

// Scratch (device globals: allocation-free per harness rules)
__device__ float g_q[(size_t)SEQ * DIMSZ];
__device__ float g_k[(size_t)SEQ * DIMSZ];
__device__ float g_v[(size_t)SEQ * DIMSZ];
__device__ float g_o[(size_t)SEQ * DIMSZ];
__device__ float g_xt[(size_t)SEQ * DIMSZ];              // tf32-rounded x
__device__ float g_wt[(size_t)4 * DIMSZ * DIMSZ];        // tf32-rounded wq,wk,wv,wo

__device__ __forceinline__ float to_tf32(float x) { return wmma::__float_to_tf32(x); }

__device__ __forceinline__ void cp16(float* s, const float* g) {
    unsigned int sa = (unsigned int)__cvta_generic_to_shared(s);
    asm volatile("cp.async.cg.shared.global [%0], [%1], 16;" :: "r"(sa), "l"(g));
}
#define CP_COMMIT() asm volatile("cp.async.commit_group;")
#define CP_WAIT1()  asm volatile("cp.async.wait_group 1;")
#define CP_WAIT0()  asm volatile("cp.async.wait_group 0;")

// ---------------------------------------------------------------------------
// Fused tf32 pre-round of x (z=0) and the 4 weights (z=1..4).
// ---------------------------------------------------------------------------
#define W4 (DIMSZ * DIMSZ / 4)
#define X4 (SEQ * DIMSZ / 4)
__global__ void cvt_all(const float4* __restrict__ x,
                        const float4* __restrict__ w0, const float4* __restrict__ w1,
                        const float4* __restrict__ w2, const float4* __restrict__ w3,
                        float4* __restrict__ xt, float4* __restrict__ wt)
{
    int z = blockIdx.z;
    int i = blockIdx.x * blockDim.x + threadIdx.x;
    const float4* src;
    float4* dst;
    int n;
    if (z == 0)      { src = x;  dst = xt;          n = X4; }
    else if (z == 1) { src = w0; dst = wt;          n = W4; }
    else if (z == 2) { src = w1; dst = wt + W4;     n = W4; }
    else if (z == 3) { src = w2; dst = wt + 2 * W4; n = W4; }
    else             { src = w3; dst = wt + 3 * W4; n = W4; }
    if (i >= n) return;
    float4 v = src[i];
    dst[i] = make_float4(to_tf32(v.x), to_tf32(v.y), to_tf32(v.z), to_tf32(v.w));
}

// ---------------------------------------------------------------------------
// GEMM: C[2048,4096] = A[2048,4096] @ B[4096,4096], TF32 tensor cores.
// Block tile 128x128, BK=32, cp.async 3-stage pipeline. 256 thr = 8 warps.
// round_out: round C to tf32 before store (for Q/K/V which feed later mmas).
// ---------------------------------------------------------------------------
#define GM 2048
#define GN 4096
#define GK 4096
#define BK 32
#define NT (GK / BK)    // 128
#define STAGES 3
#define LDA 36
#define LDB 132
#define ASTAGE (128 * LDA)
#define BSTAGE (BK * LDB)
#define GEMM_SMEM_BYTES (STAGES * (ASTAGE + BSTAGE) * 4)

__device__ __forceinline__ void issue_stage(const float* __restrict__ A,
                                            const float* __restrict__ B,
                                            float* As, float* Bs,
                                            int bm, int bn, int kk, int tid)
{
#pragma unroll
    for (int i = 0; i < 4; i++) {
        int c = tid + i * 256;
        int r = c >> 3, k4 = (c & 7) << 2;
        cp16(&As[r * LDA + k4], A + (size_t)(bm + r) * GK + kk + k4);
    }
#pragma unroll
    for (int i = 0; i < 4; i++) {
        int c = tid + i * 256;
        int r = c >> 5, c4 = (c & 31) << 2;
        cp16(&Bs[r * LDB + c4], B + (size_t)(kk + r) * GN + bn + c4);
    }
}

__device__ __forceinline__ void gemm_core(const float* __restrict__ A,
                                          const float* __restrict__ B,
                                          float* __restrict__ C,
                                          float* sm, bool round_out)
{
    float* As = sm;
    float* Bs = sm + STAGES * ASTAGE;

    const int tid = threadIdx.x;
    const int w   = tid >> 5;
    const int bm  = blockIdx.x * 128;
    const int bn  = blockIdx.y * 128;
    const int wr  = (w >> 1) * 32;
    const int wc  = (w & 1) * 64;

    wmma::fragment<wmma::accumulator, 16, 16, 8, float> acc[2][4];
#pragma unroll
    for (int i = 0; i < 2; i++)
#pragma unroll
        for (int j = 0; j < 4; j++) wmma::fill_fragment(acc[i][j], 0.0f);

    issue_stage(A, B, As, Bs, bm, bn, 0, tid);
    CP_COMMIT();
    issue_stage(A, B, As + ASTAGE, Bs + BSTAGE, bm, bn, BK, tid);
    CP_COMMIT();

    for (int t = 0; t < NT; t++) {
        CP_WAIT1();
        __syncthreads();

        int nk = t + 2;
        if (nk < NT) {
            int buf = nk % STAGES;
            issue_stage(A, B, As + buf * ASTAGE, Bs + buf * BSTAGE, bm, bn, nk * BK, tid);
        }
        CP_COMMIT();

        const float* Ac = As + (t % STAGES) * ASTAGE;
        const float* Bc = Bs + (t % STAGES) * BSTAGE;
#pragma unroll
        for (int ks = 0; ks < 4; ks++) {
            wmma::fragment<wmma::matrix_a, 16, 16, 8, wmma::precision::tf32, wmma::row_major> a[2];
            wmma::fragment<wmma::matrix_b, 16, 16, 8, wmma::precision::tf32, wmma::row_major> b[4];
#pragma unroll
            for (int i = 0; i < 2; i++)
                wmma::load_matrix_sync(a[i], &Ac[(wr + i * 16) * LDA + ks * 8], LDA);
#pragma unroll
            for (int j = 0; j < 4; j++)
                wmma::load_matrix_sync(b[j], &Bc[(ks * 8) * LDB + wc + j * 16], LDB);
#pragma unroll
            for (int i = 0; i < 2; i++)
#pragma unroll
                for (int j = 0; j < 4; j++)
                    wmma::mma_sync(acc[i][j], a[i], b[j], acc[i][j]);
        }
    }

    if (round_out) {
#pragma unroll
        for (int i = 0; i < 2; i++)
#pragma unroll
            for (int j = 0; j < 4; j++)
#pragma unroll
                for (int t = 0; t < acc[i][j].num_elements; t++)
                    acc[i][j].x[t] = to_tf32(acc[i][j].x[t]);
    }

#pragma unroll
    for (int i = 0; i < 2; i++)
#pragma unroll
        for (int j = 0; j < 4; j++)
            wmma::store_matrix_sync(C + (size_t)(bm + wr + i * 16) * GN + bn + wc + j * 16,
                                    acc[i][j], GN, wmma::mem_row_major);
}

__global__ __launch_bounds__(256, 2) void gemm_qkv(const float* __restrict__ x)
{
    extern __shared__ float sm[];
    const float* B = g_wt + (size_t)blockIdx.z * DIMSZ * DIMSZ;
    float* C = (blockIdx.z == 0) ? g_q : (blockIdx.z == 1) ? g_k : g_v;
    gemm_core(x, B, C, sm, true);   // round Q/K/V to tf32 (feeds rope & flash)
}

__global__ __launch_bounds__(256, 2) void gemm_out(const float* __restrict__ A,
                                                   float* __restrict__ C)
{
    extern __shared__ float sm[];
    gemm_core(A, g_wt + (size_t)3 * DIMSZ * DIMSZ, C, sm, false);
}

// ---------------------------------------------------------------------------
// RoPE applied in-place to g_q and g_k; outputs tf32-rounded.
// ---------------------------------------------------------------------------
__global__ void rope_kernel(const float* __restrict__ fcos, const float* __restrict__ fsin)
{
    int idx = blockIdx.x * blockDim.x + threadIdx.x;
    if (idx >= SEQ * NHEAD * (HDIM / 2)) return;
    int i = idx & 63;
    int h = (idx >> 6) & (NHEAD - 1);
    int s = idx >> 11;
    float c  = fcos[s * 64 + i];
    float sn = fsin[s * 64 + i];
    size_t off = (size_t)s * DIMSZ + h * HDIM + 2 * i;
    float q0 = g_q[off], q1 = g_q[off + 1];
    g_q[off]     = to_tf32(q0 * c - q1 * sn);
    g_q[off + 1] = to_tf32(q0 * sn + q1 * c);
    float k0 = g_k[off], k1 = g_k[off + 1];
    g_k[off]     = to_tf32(k0 * c - k1 * sn);
    g_k[off + 1] = to_tf32(k0 * sn + k1 * c);
}

// ---------------------------------------------------------------------------
// Flash attention v2: cp.async double-buffered K/V, reversed q-block order
// (long CTAs first), all inputs pre-rounded to tf32 -> raw byte copies.
// ---------------------------------------------------------------------------
#define LDQ 132   // 528B rows: 16B multiple, 4-bank row shift
#define LDS_S 72
#define FLASH_SMEM_FLOATS (6 * 64 * LDQ + 64 * LDS_S + 3 * 64)
#define FLASH_SMEM_BYTES (FLASH_SMEM_FLOATS * 4)

__global__ __launch_bounds__(256) void flash_attn()
{
    extern __shared__ float sm[];
    float* Qs   = sm;                       // 64 x LDQ
    float* Ks   = Qs + 64 * LDQ;            // 2 x 64 x LDQ (double buffer)
    float* Vs   = Ks + 2 * 64 * LDQ;        // 2 x 64 x LDQ
    float* Os   = Vs + 2 * 64 * LDQ;        // 64 x LDQ
    float* Ss   = Os + 64 * LDQ;            // 64 x LDS_S
    float* mrow = Ss + 64 * LDS_S;
    float* lrow = mrow + 64;
    float* arow = lrow + 64;

    const int qb  = (gridDim.x - 1) - blockIdx.x;   // long blocks first
    const int h   = blockIdx.y;
    const int tid = threadIdx.x;
    const int w   = tid >> 5;
    const float scale = 0.08838834764831845f;  // 1/sqrt(128)

    const float* Qg = g_q + (size_t)qb * 64 * DIMSZ + h * HDIM;
    const float* Kh = g_k + (size_t)h * HDIM;
    const float* Vh = g_v + (size_t)h * HDIM;

    // Prologue: async-load Q and K/V tile 0 as one group.
#pragma unroll
    for (int i = 0; i < 8; i++) {
        int idx = tid + i * 256;
        int r = idx >> 5, d4 = (idx & 31) << 2;
        cp16(&Qs[r * LDQ + d4], Qg + (size_t)r * DIMSZ + d4);
        cp16(&Ks[r * LDQ + d4], Kh + (size_t)r * DIMSZ + d4);
        cp16(&Vs[r * LDQ + d4], Vh + (size_t)r * DIMSZ + d4);
    }
    CP_COMMIT();

    for (int i = tid; i < 64 * LDQ; i += 256) Os[i] = 0.0f;
    if (tid < 64) { mrow[tid] = -1e30f; lrow[tid] = 0.0f; }

    for (int kt = 0; kt <= qb; kt++) {
        const int buf = kt & 1;
        // Prefetch next K/V tile into the other buffer (safe: end-of-iter
        // barrier of kt-1 guarantees its readers are done).
        if (kt + 1 <= qb) {
            float* Kn = Ks + (buf ^ 1) * 64 * LDQ;
            float* Vn = Vs + (buf ^ 1) * 64 * LDQ;
            const float* Kg = Kh + (size_t)(kt + 1) * 64 * DIMSZ;
            const float* Vg = Vh + (size_t)(kt + 1) * 64 * DIMSZ;
#pragma unroll
            for (int i = 0; i < 8; i++) {
                int idx = tid + i * 256;
                int r = idx >> 5, d4 = (idx & 31) << 2;
                cp16(&Kn[r * LDQ + d4], Kg + (size_t)r * DIMSZ + d4);
                cp16(&Vn[r * LDQ + d4], Vg + (size_t)r * DIMSZ + d4);
            }
            CP_COMMIT();
            CP_WAIT1();          // current tile's group complete
        } else {
            CP_WAIT0();
        }
        __syncthreads();

        const float* Kc = Ks + buf * 64 * LDQ;
        const float* Vc = Vs + buf * 64 * LDQ;

        // S = scale * Q @ K^T : warp grid 4x2, each warp 16x32
        {
            const int wr = (w >> 1) * 16;
            const int wc = (w & 1) * 32;
            wmma::fragment<wmma::accumulator, 16, 16, 8, float> c[2];
            wmma::fill_fragment(c[0], 0.0f);
            wmma::fill_fragment(c[1], 0.0f);
#pragma unroll
            for (int ks = 0; ks < 16; ks++) {
                wmma::fragment<wmma::matrix_a, 16, 16, 8, wmma::precision::tf32, wmma::row_major> a;
                wmma::load_matrix_sync(a, &Qs[wr * LDQ + ks * 8], LDQ);
#pragma unroll
                for (int j = 0; j < 2; j++) {
                    wmma::fragment<wmma::matrix_b, 16, 16, 8, wmma::precision::tf32, wmma::col_major> b;
                    wmma::load_matrix_sync(b, &Kc[(wc + j * 16) * LDQ + ks * 8], LDQ);
                    wmma::mma_sync(c[j], a, b, c[j]);
                }
            }
#pragma unroll
            for (int j = 0; j < 2; j++) {
#pragma unroll
                for (int t = 0; t < c[j].num_elements; t++) c[j].x[t] *= scale;
                wmma::store_matrix_sync(&Ss[wr * LDS_S + wc + j * 16], c[j], LDS_S,
                                        wmma::mem_row_major);
            }
        }
        __syncthreads();

        // Online softmax: 4 threads per row
        {
            int r   = tid >> 2;
            int sub = tid & 3;
            int smax = (kt == qb) ? (r + 1) : 64;
            float mloc = -1e30f;
            int c0 = sub * 16;
#pragma unroll
            for (int c = 0; c < 16; c++) {
                int cc = c0 + c;
                if (cc < smax) mloc = fmaxf(mloc, Ss[r * LDS_S + cc]);
            }
#pragma unroll
            for (int o = 1; o < 4; o <<= 1)
                mloc = fmaxf(mloc, __shfl_xor_sync(0xffffffffu, mloc, o));
            float mo = mrow[r];
            float mn = fmaxf(mo, mloc);
            float alpha = __expf(mo - mn);
            float lsum = 0.0f;
#pragma unroll
            for (int c = 0; c < 16; c++) {
                int cc = c0 + c;
                float p = (cc < smax) ? __expf(Ss[r * LDS_S + cc] - mn) : 0.0f;
                p = to_tf32(p);
                Ss[r * LDS_S + cc] = p;
                lsum += p;
            }
#pragma unroll
            for (int o = 1; o < 4; o <<= 1)
                lsum += __shfl_xor_sync(0xffffffffu, lsum, o);
            if (sub == 0) {
                lrow[r] = lrow[r] * alpha + lsum;
                mrow[r] = mn;
                arow[r] = alpha;
            }
        }
        __syncthreads();

        // Rescale O accumulator
        for (int i = tid; i < 64 * 128; i += 256) {
            int r = i >> 7, d = i & 127;
            Os[r * LDQ + d] *= arow[r];
        }
        __syncthreads();

        // O += P @ V : warp grid 2x4, each warp 32x32
        {
            const int wr = (w >> 2) * 32;
            const int wc = (w & 3) * 32;
            wmma::fragment<wmma::accumulator, 16, 16, 8, float> c[2][2];
#pragma unroll
            for (int i = 0; i < 2; i++)
#pragma unroll
                for (int j = 0; j < 2; j++)
                    wmma::load_matrix_sync(c[i][j], &Os[(wr + i * 16) * LDQ + wc + j * 16],
                                           LDQ, wmma::mem_row_major);
#pragma unroll
            for (int ks = 0; ks < 8; ks++) {
                wmma::fragment<wmma::matrix_a, 16, 16, 8, wmma::precision::tf32, wmma::row_major> a[2];
                wmma::fragment<wmma::matrix_b, 16, 16, 8, wmma::precision::tf32, wmma::row_major> b[2];
#pragma unroll
                for (int i = 0; i < 2; i++)
                    wmma::load_matrix_sync(a[i], &Ss[(wr + i * 16) * LDS_S + ks * 8], LDS_S);
#pragma unroll
                for (int j = 0; j < 2; j++)
                    wmma::load_matrix_sync(b[j], &Vc[(ks * 8) * LDQ + wc + j * 16], LDQ);
#pragma unroll
                for (int i = 0; i < 2; i++)
#pragma unroll
                    for (int j = 0; j < 2; j++)
                        wmma::mma_sync(c[i][j], a[i], b[j], c[i][j]);
            }
#pragma unroll
            for (int i = 0; i < 2; i++)
#pragma unroll
                for (int j = 0; j < 2; j++)
                    wmma::store_matrix_sync(&Os[(wr + i * 16) * LDQ + wc + j * 16],
                                            c[i][j], LDQ, wmma::mem_row_major);
        }
        __syncthreads();
    }

    // Epilogue: normalize, write tf32-rounded (gemm_out raw-copies it).
    float* Og = g_o + (size_t)qb * 64 * DIMSZ + h * HDIM;
    for (int i = tid; i < 64 * 128; i += 256) {
        int r = i >> 7, d = i & 127;
        Og[(size_t)r * DIMSZ + d] = to_tf32(Os[r * LDQ + d] / lrow[r]);
    }
}

// ---------------------------------------------------------------------------
extern "C" void kernel_launch(void* const* d_in, const int* in_sizes, int n_in,
                              void* d_out, int out_size)
{
    const float* x  = (const float*)d_in[0];
    const float* wq = (const float*)d_in[1];
    const float* wk = (const float*)d_in[2];
    const float* wv = (const float*)d_in[3];
    const float* wo = (const float*)d_in[4];
    const float* fc = (const float*)d_in[5];
    const float* fs = (const float*)d_in[6];
    float* out = (float*)d_out;

    float *xt, *wt, *o;
    cudaGetSymbolAddress((void**)&xt, g_xt);
    cudaGetSymbolAddress((void**)&wt, g_wt);
    cudaGetSymbolAddress((void**)&o,  g_o);

    cudaFuncSetAttribute(gemm_qkv, cudaFuncAttributeMaxDynamicSharedMemorySize,
                         GEMM_SMEM_BYTES);
    cudaFuncSetAttribute(gemm_out, cudaFuncAttributeMaxDynamicSharedMemorySize,
                         GEMM_SMEM_BYTES);
    cudaFuncSetAttribute(flash_attn, cudaFuncAttributeMaxDynamicSharedMemorySize,
                         FLASH_SMEM_BYTES);

    // 1: fused tf32 pre-round (x + 4 weights)
    dim3 cgrid((W4 + 255) / 256, 1, 5);
    cvt_all<<<cgrid, 256>>>((const float4*)x, (const float4*)wq, (const float4*)wk,
                            (const float4*)wv, (const float4*)wo,
                            (float4*)xt, (float4*)wt);

    // 2: QKV projections
    dim3 qkv_grid(GM / 128, GN / 128, 3);
    gemm_qkv<<<qkv_grid, 256, GEMM_SMEM_BYTES>>>(xt);

    // 3: RoPE
    int npairs = SEQ * NHEAD * (HDIM / 2);
    rope_kernel<<<(npairs + 255) / 256, 256>>>(fc, fs);

    // 4: flash attention  (4th launch -> ncu profiles this one)
    flash_attn<<<dim3(SEQ / 64, NHEAD), 256, FLASH_SMEM_BYTES>>>();

    // 5: output projection
    dim3 ogrid(GM / 128, GN / 128);
    gemm_out<<<ogrid, 256, GEMM_SMEM_BYTES>>>(o, out);
}

// round 7
// speedup vs baseline: 1.5449x; 1.5449x over previous
#include <cuda_runtime.h>
#include <cstdint>
#include <mma.h>

using namespace nvcuda;

#define SEQ   2048
#define DIMSZ 4096
#define NHEAD 32
#define HDIM  128

// Scratch (device globals: allocation-free per harness rules)
__device__ float g_q[(size_t)SEQ * DIMSZ];
__device__ float g_k[(size_t)SEQ * DIMSZ];
__device__ float g_v[(size_t)SEQ * DIMSZ];
__device__ float g_o[(size_t)SEQ * DIMSZ];
__device__ float g_xt[(size_t)SEQ * DIMSZ];              // tf32-rounded x
__device__ float g_wt[(size_t)4 * DIMSZ * DIMSZ];        // tf32-rounded wq,wk,wv,wo

__device__ __forceinline__ float to_tf32(float x) { return wmma::__float_to_tf32(x); }

__device__ __forceinline__ void cp16(float* s, const float* g) {
    unsigned int sa = (unsigned int)__cvta_generic_to_shared(s);
    asm volatile("cp.async.cg.shared.global [%0], [%1], 16;" :: "r"(sa), "l"(g));
}
#define CP_COMMIT() asm volatile("cp.async.commit_group;")
#define CP_WAIT1()  asm volatile("cp.async.wait_group 1;")
#define CP_WAIT0()  asm volatile("cp.async.wait_group 0;")

// ---------------------------------------------------------------------------
// Fused tf32 pre-round of x (z=0) and the 4 weights (z=1..4).
// ---------------------------------------------------------------------------
#define W4 (DIMSZ * DIMSZ / 4)
#define X4 (SEQ * DIMSZ / 4)
__global__ void cvt_all(const float4* __restrict__ x,
                        const float4* __restrict__ w0, const float4* __restrict__ w1,
                        const float4* __restrict__ w2, const float4* __restrict__ w3,
                        float4* __restrict__ xt, float4* __restrict__ wt)
{
    int z = blockIdx.z;
    int i = blockIdx.x * blockDim.x + threadIdx.x;
    const float4* src;
    float4* dst;
    int n;
    if (z == 0)      { src = x;  dst = xt;          n = X4; }
    else if (z == 1) { src = w0; dst = wt;          n = W4; }
    else if (z == 2) { src = w1; dst = wt + W4;     n = W4; }
    else if (z == 3) { src = w2; dst = wt + 2 * W4; n = W4; }
    else             { src = w3; dst = wt + 3 * W4; n = W4; }
    if (i >= n) return;
    float4 v = src[i];
    dst[i] = make_float4(to_tf32(v.x), to_tf32(v.y), to_tf32(v.z), to_tf32(v.w));
}

// ---------------------------------------------------------------------------
// GEMM: C[2048,4096] = A[2048,4096] @ B[4096,4096], TF32 tensor cores.
// Block tile 128x128, BK=32, cp.async 3-stage pipeline. 256 thr = 8 warps.
// ---------------------------------------------------------------------------
#define GM 2048
#define GN 4096
#define GK 4096
#define BK 32
#define NT (GK / BK)    // 128
#define STAGES 3
#define LDA 36
#define LDB 132
#define ASTAGE (128 * LDA)
#define BSTAGE (BK * LDB)
#define GEMM_SMEM_BYTES (STAGES * (ASTAGE + BSTAGE) * 4)

__device__ __forceinline__ void issue_stage(const float* __restrict__ A,
                                            const float* __restrict__ B,
                                            float* As, float* Bs,
                                            int bm, int bn, int kk, int tid)
{
#pragma unroll
    for (int i = 0; i < 4; i++) {
        int c = tid + i * 256;
        int r = c >> 3, k4 = (c & 7) << 2;
        cp16(&As[r * LDA + k4], A + (size_t)(bm + r) * GK + kk + k4);
    }
#pragma unroll
    for (int i = 0; i < 4; i++) {
        int c = tid + i * 256;
        int r = c >> 5, c4 = (c & 31) << 2;
        cp16(&Bs[r * LDB + c4], B + (size_t)(kk + r) * GN + bn + c4);
    }
}

__device__ __forceinline__ void gemm_core(const float* __restrict__ A,
                                          const float* __restrict__ B,
                                          float* __restrict__ C,
                                          float* sm, bool round_out)
{
    float* As = sm;
    float* Bs = sm + STAGES * ASTAGE;

    const int tid = threadIdx.x;
    const int w   = tid >> 5;
    const int bm  = blockIdx.x * 128;
    const int bn  = blockIdx.y * 128;
    const int wr  = (w >> 1) * 32;
    const int wc  = (w & 1) * 64;

    wmma::fragment<wmma::accumulator, 16, 16, 8, float> acc[2][4];
#pragma unroll
    for (int i = 0; i < 2; i++)
#pragma unroll
        for (int j = 0; j < 4; j++) wmma::fill_fragment(acc[i][j], 0.0f);

    issue_stage(A, B, As, Bs, bm, bn, 0, tid);
    CP_COMMIT();
    issue_stage(A, B, As + ASTAGE, Bs + BSTAGE, bm, bn, BK, tid);
    CP_COMMIT();

    for (int t = 0; t < NT; t++) {
        CP_WAIT1();
        __syncthreads();

        int nk = t + 2;
        if (nk < NT) {
            int buf = nk % STAGES;
            issue_stage(A, B, As + buf * ASTAGE, Bs + buf * BSTAGE, bm, bn, nk * BK, tid);
        }
        CP_COMMIT();

        const float* Ac = As + (t % STAGES) * ASTAGE;
        const float* Bc = Bs + (t % STAGES) * BSTAGE;
#pragma unroll
        for (int ks = 0; ks < 4; ks++) {
            wmma::fragment<wmma::matrix_a, 16, 16, 8, wmma::precision::tf32, wmma::row_major> a[2];
            wmma::fragment<wmma::matrix_b, 16, 16, 8, wmma::precision::tf32, wmma::row_major> b[4];
#pragma unroll
            for (int i = 0; i < 2; i++)
                wmma::load_matrix_sync(a[i], &Ac[(wr + i * 16) * LDA + ks * 8], LDA);
#pragma unroll
            for (int j = 0; j < 4; j++)
                wmma::load_matrix_sync(b[j], &Bc[(ks * 8) * LDB + wc + j * 16], LDB);
#pragma unroll
            for (int i = 0; i < 2; i++)
#pragma unroll
                for (int j = 0; j < 4; j++)
                    wmma::mma_sync(acc[i][j], a[i], b[j], acc[i][j]);
        }
    }

    if (round_out) {
#pragma unroll
        for (int i = 0; i < 2; i++)
#pragma unroll
            for (int j = 0; j < 4; j++)
#pragma unroll
                for (int t = 0; t < acc[i][j].num_elements; t++)
                    acc[i][j].x[t] = to_tf32(acc[i][j].x[t]);
    }

#pragma unroll
    for (int i = 0; i < 2; i++)
#pragma unroll
        for (int j = 0; j < 4; j++)
            wmma::store_matrix_sync(C + (size_t)(bm + wr + i * 16) * GN + bn + wc + j * 16,
                                    acc[i][j], GN, wmma::mem_row_major);
}

__global__ __launch_bounds__(256, 2) void gemm_qkv(const float* __restrict__ x)
{
    extern __shared__ float sm[];
    const float* B = g_wt + (size_t)blockIdx.z * DIMSZ * DIMSZ;
    float* C = (blockIdx.z == 0) ? g_q : (blockIdx.z == 1) ? g_k : g_v;
    gemm_core(x, B, C, sm, true);   // round Q/K/V to tf32 (feeds rope & flash)
}

__global__ __launch_bounds__(256, 2) void gemm_out(const float* __restrict__ A,
                                                   float* __restrict__ C)
{
    extern __shared__ float sm[];
    gemm_core(A, g_wt + (size_t)3 * DIMSZ * DIMSZ, C, sm, false);
}

// ---------------------------------------------------------------------------
// RoPE applied in-place to g_q and g_k; outputs tf32-rounded.
// ---------------------------------------------------------------------------
__global__ void rope_kernel(const float* __restrict__ fcos, const float* __restrict__ fsin)
{
    int idx = blockIdx.x * blockDim.x + threadIdx.x;
    if (idx >= SEQ * NHEAD * (HDIM / 2)) return;
    int i = idx & 63;
    int h = (idx >> 6) & (NHEAD - 1);
    int s = idx >> 11;
    float c  = fcos[s * 64 + i];
    float sn = fsin[s * 64 + i];
    size_t off = (size_t)s * DIMSZ + h * HDIM + 2 * i;
    float q0 = g_q[off], q1 = g_q[off + 1];
    g_q[off]     = to_tf32(q0 * c - q1 * sn);
    g_q[off + 1] = to_tf32(q0 * sn + q1 * c);
    float k0 = g_k[off], k1 = g_k[off + 1];
    g_k[off]     = to_tf32(k0 * c - k1 * sn);
    g_k[off + 1] = to_tf32(k0 * sn + k1 * c);
}

// ---------------------------------------------------------------------------
// Flash attention v3: 2 CTAs/SM. q-tile 64, k-tile 32, single-buffered
// cp.async loads. SMEM = 111.4 KB/CTA so two 8-warp CTAs co-reside and hide
// each other's barrier/load stalls.
// ---------------------------------------------------------------------------
#define BKT 32
#define LDQ 132   // 528B rows: 16B multiple
#define LDS_S 36  // 32 + 4 pad
#define FLASH_SMEM_FLOATS (2 * 64 * LDQ + 2 * BKT * LDQ + 64 * LDS_S + 3 * 64)
#define FLASH_SMEM_BYTES (FLASH_SMEM_FLOATS * 4)

__global__ __launch_bounds__(256, 2) void flash_attn()
{
    extern __shared__ float sm[];
    float* Qs   = sm;                       // 64 x LDQ
    float* Ks   = Qs + 64 * LDQ;            // 32 x LDQ
    float* Vs   = Ks + BKT * LDQ;           // 32 x LDQ
    float* Os   = Vs + BKT * LDQ;           // 64 x LDQ
    float* Ss   = Os + 64 * LDQ;            // 64 x LDS_S
    float* mrow = Ss + 64 * LDS_S;
    float* lrow = mrow + 64;
    float* arow = lrow + 64;

    const int qb  = (gridDim.x - 1) - blockIdx.x;   // long blocks first
    const int h   = blockIdx.y;
    const int tid = threadIdx.x;
    const int w   = tid >> 5;
    const float scale = 0.08838834764831845f;  // 1/sqrt(128)

    const float* Qg = g_q + (size_t)qb * 64 * DIMSZ + h * HDIM;
    const float* Kh = g_k + (size_t)h * HDIM;
    const float* Vh = g_v + (size_t)h * HDIM;

    // Prologue: async-load Q (raw copy, already tf32-rounded).
#pragma unroll
    for (int i = 0; i < 8; i++) {
        int idx = tid + i * 256;
        int r = idx >> 5, d4 = (idx & 31) << 2;
        cp16(&Qs[r * LDQ + d4], Qg + (size_t)r * DIMSZ + d4);
    }
    CP_COMMIT();

    for (int i = tid; i < 64 * LDQ; i += 256) Os[i] = 0.0f;
    if (tid < 64) { mrow[tid] = -1e30f; lrow[tid] = 0.0f; }

    const int ntiles = 2 * qb + 2;   // 32-row k-tiles up to and incl. diagonal

    for (int kt = 0; kt < ntiles; kt++) {
        // Load K/V tile (32 x 128): 1024 16B chunks, 4/thread each
        const float* Kg = Kh + (size_t)kt * BKT * DIMSZ;
        const float* Vg = Vh + (size_t)kt * BKT * DIMSZ;
#pragma unroll
        for (int i = 0; i < 4; i++) {
            int idx = tid + i * 256;
            int r = idx >> 5, d4 = (idx & 31) << 2;
            cp16(&Ks[r * LDQ + d4], Kg + (size_t)r * DIMSZ + d4);
            cp16(&Vs[r * LDQ + d4], Vg + (size_t)r * DIMSZ + d4);
        }
        CP_COMMIT();
        CP_WAIT0();
        __syncthreads();

        // S = scale * Q @ K^T : warp grid 4x2, each warp 16 rows x 16 cols
        {
            const int wr = (w >> 1) * 16;
            const int wc = (w & 1) * 16;
            wmma::fragment<wmma::accumulator, 16, 16, 8, float> c;
            wmma::fill_fragment(c, 0.0f);
#pragma unroll
            for (int ks = 0; ks < 16; ks++) {
                wmma::fragment<wmma::matrix_a, 16, 16, 8, wmma::precision::tf32, wmma::row_major> a;
                wmma::fragment<wmma::matrix_b, 16, 16, 8, wmma::precision::tf32, wmma::col_major> b;
                wmma::load_matrix_sync(a, &Qs[wr * LDQ + ks * 8], LDQ);
                wmma::load_matrix_sync(b, &Ks[wc * LDQ + ks * 8], LDQ);
                wmma::mma_sync(c, a, b, c);
            }
#pragma unroll
            for (int t = 0; t < c.num_elements; t++) c.x[t] *= scale;
            wmma::store_matrix_sync(&Ss[wr * LDS_S + wc], c, LDS_S, wmma::mem_row_major);
        }
        __syncthreads();

        // Online softmax: 4 threads per row, 8 cols each
        {
            int r   = tid >> 2;
            int sub = tid & 3;
            int lim = qb * 64 + r - kt * BKT;           // max valid col (global causal)
            int smax = lim + 1;
            if (smax > BKT) smax = BKT;
            if (smax < 0)   smax = 0;
            float mloc = -1e30f;
            int c0 = sub * 8;
#pragma unroll
            for (int c = 0; c < 8; c++) {
                int cc = c0 + c;
                if (cc < smax) mloc = fmaxf(mloc, Ss[r * LDS_S + cc]);
            }
#pragma unroll
            for (int o = 1; o < 4; o <<= 1)
                mloc = fmaxf(mloc, __shfl_xor_sync(0xffffffffu, mloc, o));
            float mo = mrow[r];
            float mn = fmaxf(mo, mloc);
            float alpha = __expf(mo - mn);
            float lsum = 0.0f;
#pragma unroll
            for (int c = 0; c < 8; c++) {
                int cc = c0 + c;
                float p = (cc < smax) ? __expf(Ss[r * LDS_S + cc] - mn) : 0.0f;
                p = to_tf32(p);
                Ss[r * LDS_S + cc] = p;
                lsum += p;
            }
#pragma unroll
            for (int o = 1; o < 4; o <<= 1)
                lsum += __shfl_xor_sync(0xffffffffu, lsum, o);
            if (sub == 0) {
                lrow[r] = lrow[r] * alpha + lsum;
                mrow[r] = mn;
                arow[r] = alpha;
            }
        }
        __syncthreads();

        // Rescale O accumulator
        for (int i = tid; i < 64 * 128; i += 256) {
            int r = i >> 7, d = i & 127;
            Os[r * LDQ + d] *= arow[r];
        }
        __syncthreads();

        // O += P @ V : warp grid 2x4, each warp 32x32, k-steps = 4
        {
            const int wr = (w >> 2) * 32;
            const int wc = (w & 3) * 32;
            wmma::fragment<wmma::accumulator, 16, 16, 8, float> c[2][2];
#pragma unroll
            for (int i = 0; i < 2; i++)
#pragma unroll
                for (int j = 0; j < 2; j++)
                    wmma::load_matrix_sync(c[i][j], &Os[(wr + i * 16) * LDQ + wc + j * 16],
                                           LDQ, wmma::mem_row_major);
#pragma unroll
            for (int ks = 0; ks < 4; ks++) {
                wmma::fragment<wmma::matrix_a, 16, 16, 8, wmma::precision::tf32, wmma::row_major> a[2];
                wmma::fragment<wmma::matrix_b, 16, 16, 8, wmma::precision::tf32, wmma::row_major> b[2];
#pragma unroll
                for (int i = 0; i < 2; i++)
                    wmma::load_matrix_sync(a[i], &Ss[(wr + i * 16) * LDS_S + ks * 8], LDS_S);
#pragma unroll
                for (int j = 0; j < 2; j++)
                    wmma::load_matrix_sync(b[j], &Vs[(ks * 8) * LDQ + wc + j * 16], LDQ);
#pragma unroll
                for (int i = 0; i < 2; i++)
#pragma unroll
                    for (int j = 0; j < 2; j++)
                        wmma::mma_sync(c[i][j], a[i], b[j], c[i][j]);
            }
#pragma unroll
            for (int i = 0; i < 2; i++)
#pragma unroll
                for (int j = 0; j < 2; j++)
                    wmma::store_matrix_sync(&Os[(wr + i * 16) * LDQ + wc + j * 16],
                                            c[i][j], LDQ, wmma::mem_row_major);
        }
        __syncthreads();
    }

    // Epilogue: normalize, write tf32-rounded (gemm_out raw-copies it).
    float* Og = g_o + (size_t)qb * 64 * DIMSZ + h * HDIM;
    for (int i = tid; i < 64 * 128; i += 256) {
        int r = i >> 7, d = i & 127;
        Og[(size_t)r * DIMSZ + d] = to_tf32(Os[r * LDQ + d] / lrow[r]);
    }
}

// ---------------------------------------------------------------------------
extern "C" void kernel_launch(void* const* d_in, const int* in_sizes, int n_in,
                              void* d_out, int out_size)
{
    const float* x  = (const float*)d_in[0];
    const float* wq = (const float*)d_in[1];
    const float* wk = (const float*)d_in[2];
    const float* wv = (const float*)d_in[3];
    const float* wo = (const float*)d_in[4];
    const float* fc = (const float*)d_in[5];
    const float* fs = (const float*)d_in[6];
    float* out = (float*)d_out;

    float *xt, *wt, *o;
    cudaGetSymbolAddress((void**)&xt, g_xt);
    cudaGetSymbolAddress((void**)&wt, g_wt);
    cudaGetSymbolAddress((void**)&o,  g_o);

    cudaFuncSetAttribute(gemm_qkv, cudaFuncAttributeMaxDynamicSharedMemorySize,
                         GEMM_SMEM_BYTES);
    cudaFuncSetAttribute(gemm_out, cudaFuncAttributeMaxDynamicSharedMemorySize,
                         GEMM_SMEM_BYTES);
    cudaFuncSetAttribute(flash_attn, cudaFuncAttributeMaxDynamicSharedMemorySize,
                         FLASH_SMEM_BYTES);

    // 1: fused tf32 pre-round (x + 4 weights)
    dim3 cgrid((W4 + 255) / 256, 1, 5);
    cvt_all<<<cgrid, 256>>>((const float4*)x, (const float4*)wq, (const float4*)wk,
                            (const float4*)wv, (const float4*)wo,
                            (float4*)xt, (float4*)wt);

    // 2: QKV projections
    dim3 qkv_grid(GM / 128, GN / 128, 3);
    gemm_qkv<<<qkv_grid, 256, GEMM_SMEM_BYTES>>>(xt);

    // 3: RoPE
    int npairs = SEQ * NHEAD * (HDIM / 2);
    rope_kernel<<<(npairs + 255) / 256, 256>>>(fc, fs);

    // 4: flash attention  (4th launch -> ncu profiles this one)
    flash_attn<<<dim3(SEQ / 64, NHEAD), 256, FLASH_SMEM_BYTES>>>();

    // 5: output projection
    dim3 ogrid(GM / 128, GN / 128);
    gemm_out<<<ogrid, 256, GEMM_SMEM_BYTES>>>(o, out);
}

// round 9
// speedup vs baseline: 1.6009x; 1.0362x over previous
#include <cuda_runtime.h>
#include <cstdint>
#include <mma.h>

using namespace nvcuda;

#define SEQ   2048
#define DIMSZ 4096
#define NHEAD 32
#define HDIM  128

// Scratch (device globals: allocation-free per harness rules)
__device__ float g_q[(size_t)SEQ * DIMSZ];
__device__ float g_k[(size_t)SEQ * DIMSZ];
__device__ float g_v[(size_t)SEQ * DIMSZ];
__device__ float g_o[(size_t)SEQ * DIMSZ];
__device__ float g_xt[(size_t)SEQ * DIMSZ];              // tf32-rounded x
__device__ float g_wt[(size_t)4 * DIMSZ * DIMSZ];        // tf32-rounded wq,wk,wv,wo

__device__ __forceinline__ float to_tf32(float x) { return wmma::__float_to_tf32(x); }

__device__ __forceinline__ void cp16(void* s, const float* g) {
    unsigned int sa = (unsigned int)__cvta_generic_to_shared(s);
    asm volatile("cp.async.cg.shared.global [%0], [%1], 16;" :: "r"(sa), "l"(g));
}
#define CP_COMMIT() asm volatile("cp.async.commit_group;")
#define CP_WAITG(n) asm volatile("cp.async.wait_group %0;" :: "n"(n))

// ---------------------------------------------------------------------------
// Fused tf32 pre-round of x (z=0) and the 4 weights (z=1..4).
// ---------------------------------------------------------------------------
#define W4 (DIMSZ * DIMSZ / 4)
#define X4 (SEQ * DIMSZ / 4)
__global__ void cvt_all(const float4* __restrict__ x,
                        const float4* __restrict__ w0, const float4* __restrict__ w1,
                        const float4* __restrict__ w2, const float4* __restrict__ w3,
                        float4* __restrict__ xt, float4* __restrict__ wt)
{
    int z = blockIdx.z;
    int i = blockIdx.x * blockDim.x + threadIdx.x;
    const float4* src;
    float4* dst;
    int n;
    if (z == 0)      { src = x;  dst = xt;          n = X4; }
    else if (z == 1) { src = w0; dst = wt;          n = W4; }
    else if (z == 2) { src = w1; dst = wt + W4;     n = W4; }
    else if (z == 3) { src = w2; dst = wt + 2 * W4; n = W4; }
    else             { src = w3; dst = wt + 3 * W4; n = W4; }
    if (i >= n) return;
    float4 v = src[i];
    dst[i] = make_float4(to_tf32(v.x), to_tf32(v.y), to_tf32(v.z), to_tf32(v.w));
}

// ---------------------------------------------------------------------------
// GEMM: C[2048,4096] = A[2048,4096] @ B[4096,4096], TF32 wmma.
// Block tile 128x128, BK=32, cp.async 3-stage pipeline. 256 thr = 8 warps.
// ---------------------------------------------------------------------------
#define GM 2048
#define GN 4096
#define GK 4096
#define BK 32
#define NT (GK / BK)    // 128
#define STAGES 3
#define LDA 36
#define LDB 132
#define ASTAGE (128 * LDA)
#define BSTAGE (BK * LDB)
#define GEMM_SMEM_BYTES (STAGES * (ASTAGE + BSTAGE) * 4)

__device__ __forceinline__ void issue_stage(const float* __restrict__ A,
                                            const float* __restrict__ B,
                                            float* As, float* Bs,
                                            int bm, int bn, int kk, int tid)
{
#pragma unroll
    for (int i = 0; i < 4; i++) {
        int c = tid + i * 256;
        int r = c >> 3, k4 = (c & 7) << 2;
        cp16(&As[r * LDA + k4], A + (size_t)(bm + r) * GK + kk + k4);
    }
#pragma unroll
    for (int i = 0; i < 4; i++) {
        int c = tid + i * 256;
        int r = c >> 5, c4 = (c & 31) << 2;
        cp16(&Bs[r * LDB + c4], B + (size_t)(kk + r) * GN + bn + c4);
    }
}

__device__ __forceinline__ void gemm_core(const float* __restrict__ A,
                                          const float* __restrict__ B,
                                          float* __restrict__ C,
                                          float* sm, bool round_out)
{
    float* As = sm;
    float* Bs = sm + STAGES * ASTAGE;

    const int tid = threadIdx.x;
    const int w   = tid >> 5;
    const int bm  = blockIdx.x * 128;
    const int bn  = blockIdx.y * 128;
    const int wr  = (w >> 1) * 32;
    const int wc  = (w & 1) * 64;

    wmma::fragment<wmma::accumulator, 16, 16, 8, float> acc[2][4];
#pragma unroll
    for (int i = 0; i < 2; i++)
#pragma unroll
        for (int j = 0; j < 4; j++) wmma::fill_fragment(acc[i][j], 0.0f);

    issue_stage(A, B, As, Bs, bm, bn, 0, tid);
    CP_COMMIT();
    issue_stage(A, B, As + ASTAGE, Bs + BSTAGE, bm, bn, BK, tid);
    CP_COMMIT();

    for (int t = 0; t < NT; t++) {
        CP_WAITG(1);
        __syncthreads();

        int nk = t + 2;
        if (nk < NT) {
            int buf = nk % STAGES;
            issue_stage(A, B, As + buf * ASTAGE, Bs + buf * BSTAGE, bm, bn, nk * BK, tid);
        }
        CP_COMMIT();

        const float* Ac = As + (t % STAGES) * ASTAGE;
        const float* Bc = Bs + (t % STAGES) * BSTAGE;
#pragma unroll
        for (int ks = 0; ks < 4; ks++) {
            wmma::fragment<wmma::matrix_a, 16, 16, 8, wmma::precision::tf32, wmma::row_major> a[2];
            wmma::fragment<wmma::matrix_b, 16, 16, 8, wmma::precision::tf32, wmma::row_major> b[4];
#pragma unroll
            for (int i = 0; i < 2; i++)
                wmma::load_matrix_sync(a[i], &Ac[(wr + i * 16) * LDA + ks * 8], LDA);
#pragma unroll
            for (int j = 0; j < 4; j++)
                wmma::load_matrix_sync(b[j], &Bc[(ks * 8) * LDB + wc + j * 16], LDB);
#pragma unroll
            for (int i = 0; i < 2; i++)
#pragma unroll
                for (int j = 0; j < 4; j++)
                    wmma::mma_sync(acc[i][j], a[i], b[j], acc[i][j]);
        }
    }

    if (round_out) {
#pragma unroll
        for (int i = 0; i < 2; i++)
#pragma unroll
            for (int j = 0; j < 4; j++)
#pragma unroll
                for (int t = 0; t < acc[i][j].num_elements; t++)
                    acc[i][j].x[t] = to_tf32(acc[i][j].x[t]);
    }

#pragma unroll
    for (int i = 0; i < 2; i++)
#pragma unroll
        for (int j = 0; j < 4; j++)
            wmma::store_matrix_sync(C + (size_t)(bm + wr + i * 16) * GN + bn + wc + j * 16,
                                    acc[i][j], GN, wmma::mem_row_major);
}

__global__ __launch_bounds__(256, 2) void gemm_qkv(const float* __restrict__ x)
{
    extern __shared__ float sm[];
    const float* B = g_wt + (size_t)blockIdx.z * DIMSZ * DIMSZ;
    float* C = (blockIdx.z == 0) ? g_q : (blockIdx.z == 1) ? g_k : g_v;
    gemm_core(x, B, C, sm, true);   // round Q/K/V to tf32 (feeds rope & flash)
}

__global__ __launch_bounds__(256, 2) void gemm_out(const float* __restrict__ A,
                                                   float* __restrict__ C)
{
    extern __shared__ float sm[];
    gemm_core(A, g_wt + (size_t)3 * DIMSZ * DIMSZ, C, sm, false);
}

// ---------------------------------------------------------------------------
// RoPE applied in-place to g_q and g_k; outputs tf32-rounded.
// ---------------------------------------------------------------------------
__global__ void rope_kernel(const float* __restrict__ fcos, const float* __restrict__ fsin)
{
    int idx = blockIdx.x * blockDim.x + threadIdx.x;
    if (idx >= SEQ * NHEAD * (HDIM / 2)) return;
    int i = idx & 63;
    int h = (idx >> 6) & (NHEAD - 1);
    int s = idx >> 11;
    float c  = fcos[s * 64 + i];
    float sn = fsin[s * 64 + i];
    size_t off = (size_t)s * DIMSZ + h * HDIM + 2 * i;
    float q0 = g_q[off], q1 = g_q[off + 1];
    g_q[off]     = to_tf32(q0 * c - q1 * sn);
    g_q[off + 1] = to_tf32(q0 * sn + q1 * c);
    float k0 = g_k[off], k1 = g_k[off + 1];
    g_k[off]     = to_tf32(k0 * c - k1 * sn);
    g_k[off + 1] = to_tf32(k0 * sn + k1 * c);
}

// ---------------------------------------------------------------------------
// Flash attention v4: register-resident O accumulator + double-buffered K/V.
// 2 CTAs/SM (111.4 KB). Per iter: 4 barriers, no O smem traffic.
// Accumulator fragment row mapping (sm_80+ m16n16 f32): elem e of lane t ->
// row = t/4 + 8*((e&3)>=2).
// ---------------------------------------------------------------------------
#define BKT 32
#define LDQ 132
#define LDS_S 36
#define FLASH_SMEM_FLOATS (64 * LDQ + 4 * BKT * LDQ + 64 * LDS_S + 3 * 64)
#define FLASH_SMEM_BYTES (FLASH_SMEM_FLOATS * 4)

__global__ __launch_bounds__(256, 2) void flash_attn()
{
    extern __shared__ float smf[];
    float* Qs   = smf;                      // 64 x LDQ
    float* Ks   = Qs + 64 * LDQ;            // 2 x 32 x LDQ
    float* Vs   = Ks + 2 * BKT * LDQ;       // 2 x 32 x LDQ
    float* Ss   = Vs + 2 * BKT * LDQ;       // 64 x LDS_S
    float* mrow = Ss + 64 * LDS_S;
    float* lrow = mrow + 64;
    float* arow = lrow + 64;

    const int qb   = (gridDim.x - 1) - blockIdx.x;   // long blocks first
    const int h    = blockIdx.y;
    const int tid  = threadIdx.x;
    const int w    = tid >> 5;
    const int lane = tid & 31;
    const float scale = 0.08838834764831845f;  // 1/sqrt(128)

    const float* Qg = g_q + (size_t)qb * 64 * DIMSZ + h * HDIM;
    const float* Kh = g_k + (size_t)h * HDIM;
    const float* Vh = g_v + (size_t)h * HDIM;

    // O ownership (PV warp grid 2x4): warp w -> rows owr..owr+31, cols owc..owc+31
    const int owr = (w >> 2) * 32;
    const int owc = (w & 3) * 32;
    wmma::fragment<wmma::accumulator, 16, 16, 8, float> oacc[2][2];
#pragma unroll
    for (int i = 0; i < 2; i++)
#pragma unroll
        for (int j = 0; j < 2; j++) wmma::fill_fragment(oacc[i][j], 0.0f);

    // Prologue: Q (2048 chunks) + K0/V0 (1024 chunks each) as one group.
#pragma unroll
    for (int i = 0; i < 8; i++) {
        int idx = tid + i * 256;
        int r = idx >> 5, d4 = (idx & 31) << 2;
        cp16(&Qs[r * LDQ + d4], Qg + (size_t)r * DIMSZ + d4);
    }
#pragma unroll
    for (int i = 0; i < 4; i++) {
        int idx = tid + i * 256;
        int r = idx >> 5, d4 = (idx & 31) << 2;
        cp16(&Ks[r * LDQ + d4], Kh + (size_t)r * DIMSZ + d4);
        cp16(&Vs[r * LDQ + d4], Vh + (size_t)r * DIMSZ + d4);
    }
    CP_COMMIT();

    if (tid < 64) { mrow[tid] = -1e30f; lrow[tid] = 0.0f; }

    const int ntiles = 2 * qb + 2;

    for (int kt = 0; kt < ntiles; kt++) {
        const int buf = kt & 1;

        // Prefetch next K/V into other buffer (its last readers finished at
        // the previous iteration's trailing barrier).
        if (kt + 1 < ntiles) {
            float* Kn = Ks + (buf ^ 1) * BKT * LDQ;
            float* Vn = Vs + (buf ^ 1) * BKT * LDQ;
            const float* Kg = Kh + (size_t)(kt + 1) * BKT * DIMSZ;
            const float* Vg = Vh + (size_t)(kt + 1) * BKT * DIMSZ;
#pragma unroll
            for (int i = 0; i < 4; i++) {
                int idx = tid + i * 256;
                int r = idx >> 5, d4 = (idx & 31) << 2;
                cp16(&Kn[r * LDQ + d4], Kg + (size_t)r * DIMSZ + d4);
                cp16(&Vn[r * LDQ + d4], Vg + (size_t)r * DIMSZ + d4);
            }
            CP_COMMIT();
            CP_WAITG(1);    // current tile's group done; prefetch in flight
        } else {
            CP_WAITG(0);
        }
        __syncthreads();    // A: current K/V (+Q on first iter) visible

        const float* Kc = Ks + buf * BKT * LDQ;
        const float* Vc = Vs + buf * BKT * LDQ;

        // S = scale * Q @ K^T : warp grid 4x2, each warp 16x16
        {
            const int wr = (w >> 1) * 16;
            const int wc = (w & 1) * 16;
            wmma::fragment<wmma::accumulator, 16, 16, 8, float> c;
            wmma::fill_fragment(c, 0.0f);
#pragma unroll
            for (int ks = 0; ks < 16; ks++) {
                wmma::fragment<wmma::matrix_a, 16, 16, 8, wmma::precision::tf32, wmma::row_major> a;
                wmma::fragment<wmma::matrix_b, 16, 16, 8, wmma::precision::tf32, wmma::col_major> b;
                wmma::load_matrix_sync(a, &Qs[wr * LDQ + ks * 8], LDQ);
                wmma::load_matrix_sync(b, &Kc[wc * LDQ + ks * 8], LDQ);
                wmma::mma_sync(c, a, b, c);
            }
#pragma unroll
            for (int t = 0; t < c.num_elements; t++) c.x[t] *= scale;
            wmma::store_matrix_sync(&Ss[wr * LDS_S + wc], c, LDS_S, wmma::mem_row_major);
        }
        __syncthreads();    // 1: S visible

        // Online softmax: 4 threads per row, 8 cols each
        {
            int r   = tid >> 2;
            int sub = tid & 3;
            int lim = qb * 64 + r - kt * BKT;
            int smax = lim + 1;
            if (smax > BKT) smax = BKT;
            if (smax < 0)   smax = 0;
            float mloc = -1e30f;
            int c0 = sub * 8;
#pragma unroll
            for (int c = 0; c < 8; c++) {
                int cc = c0 + c;
                if (cc < smax) mloc = fmaxf(mloc, Ss[r * LDS_S + cc]);
            }
#pragma unroll
            for (int o = 1; o < 4; o <<= 1)
                mloc = fmaxf(mloc, __shfl_xor_sync(0xffffffffu, mloc, o));
            float mo = mrow[r];
            float mn = fmaxf(mo, mloc);
            float alpha = __expf(mo - mn);
            float lsum = 0.0f;
#pragma unroll
            for (int c = 0; c < 8; c++) {
                int cc = c0 + c;
                float p = (cc < smax) ? __expf(Ss[r * LDS_S + cc] - mn) : 0.0f;
                p = to_tf32(p);
                Ss[r * LDS_S + cc] = p;
                lsum += p;
            }
#pragma unroll
            for (int o = 1; o < 4; o <<= 1)
                lsum += __shfl_xor_sync(0xffffffffu, lsum, o);
            if (sub == 0) {
                lrow[r] = lrow[r] * alpha + lsum;
                mrow[r] = mn;
                arow[r] = alpha;
            }
        }
        __syncthreads();    // 2: P + arow visible

        // Rescale O accumulator IN REGISTERS (row map: lane/4 (+8 for e%4>=2))
        {
            const int r0 = lane >> 2;
#pragma unroll
            for (int i = 0; i < 2; i++) {
                float a0 = arow[owr + i * 16 + r0];
                float a1 = arow[owr + i * 16 + r0 + 8];
#pragma unroll
                for (int j = 0; j < 2; j++)
#pragma unroll
                    for (int e = 0; e < 8; e++)
                        oacc[i][j].x[e] *= ((e & 3) >= 2) ? a1 : a0;
            }
        }

        // O += P @ V : warp grid 2x4, each warp 32x32, 4 k-steps
        {
#pragma unroll
            for (int ks = 0; ks < 4; ks++) {
                wmma::fragment<wmma::matrix_a, 16, 16, 8, wmma::precision::tf32, wmma::row_major> a[2];
                wmma::fragment<wmma::matrix_b, 16, 16, 8, wmma::precision::tf32, wmma::row_major> b[2];
#pragma unroll
                for (int i = 0; i < 2; i++)
                    wmma::load_matrix_sync(a[i], &Ss[(owr + i * 16) * LDS_S + ks * 8], LDS_S);
#pragma unroll
                for (int j = 0; j < 2; j++)
                    wmma::load_matrix_sync(b[j], &Vc[(ks * 8) * LDQ + owc + j * 16], LDQ);
#pragma unroll
                for (int i = 0; i < 2; i++)
#pragma unroll
                    for (int j = 0; j < 2; j++)
                        wmma::mma_sync(oacc[i][j], a[i], b[j], oacc[i][j]);
            }
        }
        __syncthreads();    // 3: Ss/Vs/Kc readers done -> next iter may overwrite
    }

    // Epilogue: normalize in registers, tf32-round, store direct to gmem.
    float* Og = g_o + (size_t)qb * 64 * DIMSZ + h * HDIM;
    {
        const int r0 = lane >> 2;
#pragma unroll
        for (int i = 0; i < 2; i++) {
            float inv0 = 1.0f / lrow[owr + i * 16 + r0];
            float inv1 = 1.0f / lrow[owr + i * 16 + r0 + 8];
#pragma unroll
            for (int j = 0; j < 2; j++) {
#pragma unroll
                for (int e = 0; e < 8; e++)
                    oacc[i][j].x[e] = to_tf32(oacc[i][j].x[e] *
                                              (((e & 3) >= 2) ? inv1 : inv0));
                wmma::store_matrix_sync(Og + (size_t)(owr + i * 16) * DIMSZ + owc + j * 16,
                                        oacc[i][j], DIMSZ, wmma::mem_row_major);
            }
        }
    }
}

// ---------------------------------------------------------------------------
extern "C" void kernel_launch(void* const* d_in, const int* in_sizes, int n_in,
                              void* d_out, int out_size)
{
    const float* x  = (const float*)d_in[0];
    const float* wq = (const float*)d_in[1];
    const float* wk = (const float*)d_in[2];
    const float* wv = (const float*)d_in[3];
    const float* wo = (const float*)d_in[4];
    const float* fc = (const float*)d_in[5];
    const float* fs = (const float*)d_in[6];
    float* out = (float*)d_out;

    float *xt, *wt, *o;
    cudaGetSymbolAddress((void**)&xt, g_xt);
    cudaGetSymbolAddress((void**)&wt, g_wt);
    cudaGetSymbolAddress((void**)&o,  g_o);

    cudaFuncSetAttribute(gemm_qkv, cudaFuncAttributeMaxDynamicSharedMemorySize,
                         GEMM_SMEM_BYTES);
    cudaFuncSetAttribute(gemm_out, cudaFuncAttributeMaxDynamicSharedMemorySize,
                         GEMM_SMEM_BYTES);
    cudaFuncSetAttribute(flash_attn, cudaFuncAttributeMaxDynamicSharedMemorySize,
                         FLASH_SMEM_BYTES);

    // 1: fused tf32 pre-round (x + 4 weights)
    dim3 cgrid((W4 + 255) / 256, 1, 5);
    cvt_all<<<cgrid, 256>>>((const float4*)x, (const float4*)wq, (const float4*)wk,
                            (const float4*)wv, (const float4*)wo,
                            (float4*)xt, (float4*)wt);

    // 2: QKV projections
    dim3 qkv_grid(GM / 128, GN / 128, 3);
    gemm_qkv<<<qkv_grid, 256, GEMM_SMEM_BYTES>>>(xt);

    // 3: RoPE
    int npairs = SEQ * NHEAD * (HDIM / 2);
    rope_kernel<<<(npairs + 255) / 256, 256>>>(fc, fs);

    // 4: flash attention  (4th launch -> ncu profiles this one)
    flash_attn<<<dim3(SEQ / 64, NHEAD), 256, FLASH_SMEM_BYTES>>>();

    // 5: output projection
    dim3 ogrid(GM / 128, GN / 128);
    gemm_out<<<ogrid, 256, GEMM_SMEM_BYTES>>>(o, out);
}